// round 5
// baseline (speedup 1.0000x reference)
#include <cuda_runtime.h>

#define N_NODES 100000
#define E_EDGES 1600000
#define D_IN  256
#define D_H1  128
#define D_H2  64
#define N_CLS 40

// ---------------- scratch (device globals; referenced ONLY in device code) --
__device__ int g_is64;
__device__ __align__(16) int   g_src[E_EDGES];
__device__ __align__(16) int   g_dst[E_EDGES];
__device__ __align__(16) float g_dinv[N_NODES];
__device__ __align__(16) float g_norm[E_EDGES];
__device__ __align__(16) float g_h1[N_NODES * D_H1];
__device__ __align__(16) float g_msg1[N_NODES * D_H1];
__device__ __align__(16) float g_h2[N_NODES * D_H2];
__device__ __align__(16) float g_msg2[N_NODES * D_H2];

// ---------------- dtype detection (robustness; ~free) ----------------------
__global__ void detect_kernel(const unsigned int* __restrict__ ei_raw) {
    __shared__ int any_nonzero;
    if (threadIdx.x == 0) any_nonzero = 0;
    __syncthreads();
    int nz = 0;
    for (int k = threadIdx.x; k < 1024; k += blockDim.x)
        nz |= (ei_raw[2 * k + 1] != 0u);
    if (nz) atomicOr(&any_nonzero, 1);
    __syncthreads();
    if (threadIdx.x == 0) g_is64 = (any_nonzero == 0) ? 1 : 0;
}

__global__ void convert_idx(const void* __restrict__ ei_raw) {
    int e = blockIdx.x * blockDim.x + threadIdx.x;
    if (e >= E_EDGES) return;
    if (g_is64) {
        const long long* p = (const long long*)ei_raw;
        g_src[e] = (int)p[e];
        g_dst[e] = (int)p[E_EDGES + e];
    } else {
        const int* p = (const int*)ei_raw;
        g_src[e] = p[e];
        g_dst[e] = p[E_EDGES + e];
    }
}

// ---------------- zero accumulators ----------------------------------------
__global__ void zero_bufs() {
    int i = blockIdx.x * blockDim.x + threadIdx.x;
    const int n1 = N_NODES * D_H1 / 4;
    const int n2 = N_NODES * D_H2 / 4;
    float4 z = make_float4(0.f, 0.f, 0.f, 0.f);
    if (i < n1) ((float4*)g_msg1)[i] = z;
    if (i < n2) ((float4*)g_msg2)[i] = z;
    if (i < N_NODES) g_dinv[i] = 0.f;
}

// ---------------- degree / norm --------------------------------------------
__global__ void deg_kernel(const float* __restrict__ ew) {
    int e = blockIdx.x * blockDim.x + threadIdx.x;
    if (e < E_EDGES) atomicAdd(&g_dinv[g_dst[e]], ew[e]);
}

__global__ void dinv_kernel() {
    int i = blockIdx.x * blockDim.x + threadIdx.x;
    if (i < N_NODES) g_dinv[i] = rsqrtf(g_dinv[i] + 1.0f);
}

__global__ void norm_kernel(const float* __restrict__ ew) {
    int e = blockIdx.x * blockDim.x + threadIdx.x;
    if (e < E_EDGES)
        g_norm[e] = g_dinv[g_src[e]] * ew[e] * g_dinv[g_dst[e]];
}

// ---------------- tiled fp32 GEMM body: C = A[M,K] @ W[K,Nc] (+bias) -------
__device__ __forceinline__ void gemm_body(const float* __restrict__ A,
                                          const float* __restrict__ W,
                                          float* __restrict__ C,
                                          int M, int K, int Nc,
                                          const float* __restrict__ bias) {
    const int BM = 64, BN = 64, BK = 16;
    __shared__ float As[16][64];
    __shared__ float Ws[16][64];

    const int tid = threadIdx.x;
    const int bm = blockIdx.x * BM;
    const int bn = blockIdx.y * BN;
    const int ty = tid >> 4;
    const int tx = tid & 15;

    float acc[4][4];
#pragma unroll
    for (int i = 0; i < 4; i++)
#pragma unroll
        for (int j = 0; j < 4; j++) acc[i][j] = 0.f;

    for (int kt = 0; kt < K; kt += BK) {
        {
            int ar = tid >> 2;
            int ac = (tid & 3) * 4;
            int row = bm + ar;
            float4 a = make_float4(0.f, 0.f, 0.f, 0.f);
            if (row < M)
                a = *(const float4*)(A + (size_t)row * K + kt + ac);
            As[ac + 0][ar] = a.x;
            As[ac + 1][ar] = a.y;
            As[ac + 2][ar] = a.z;
            As[ac + 3][ar] = a.w;
        }
        {
            int wr = tid >> 4;
            int wc = (tid & 15) * 4;
            float4 w = make_float4(0.f, 0.f, 0.f, 0.f);
            if (bn + wc < Nc)
                w = *(const float4*)(W + (size_t)(kt + wr) * Nc + bn + wc);
            Ws[wr][wc + 0] = w.x;
            Ws[wr][wc + 1] = w.y;
            Ws[wr][wc + 2] = w.z;
            Ws[wr][wc + 3] = w.w;
        }
        __syncthreads();

#pragma unroll
        for (int k = 0; k < BK; k++) {
            float ra[4], rb[4];
#pragma unroll
            for (int i = 0; i < 4; i++) ra[i] = As[k][ty * 4 + i];
#pragma unroll
            for (int j = 0; j < 4; j++) rb[j] = Ws[k][tx * 4 + j];
#pragma unroll
            for (int i = 0; i < 4; i++)
#pragma unroll
                for (int j = 0; j < 4; j++) acc[i][j] += ra[i] * rb[j];
        }
        __syncthreads();
    }

#pragma unroll
    for (int i = 0; i < 4; i++) {
        int row = bm + ty * 4 + i;
        if (row >= M) continue;
#pragma unroll
        for (int j = 0; j < 4; j++) {
            int col = bn + tx * 4 + j;
            if (col < Nc) {
                float v = acc[i][j];
                if (bias) v += bias[col];
                C[(size_t)row * Nc + col] = v;
            }
        }
    }
}

// GEMM wrappers: scratch symbols resolved in DEVICE code (never host args).
__global__ void gemm_l1(const float* __restrict__ x, const float* __restrict__ W1) {
    gemm_body(x, W1, g_h1, N_NODES, D_IN, D_H1, (const float*)0);
}
__global__ void gemm_l2(const float* __restrict__ W2) {
    gemm_body(g_h1, W2, g_h2, N_NODES, D_H1, D_H2, (const float*)0);
}
__global__ void gemm_l3(const float* __restrict__ Wc, const float* __restrict__ bc,
                        float* __restrict__ out) {
    gemm_body(g_h2, Wc, out, N_NODES, D_H2, N_CLS, bc);
}

// ---------------- vector reduction helper -----------------------------------
__device__ __forceinline__ void red_v4(float* p, float a, float b, float c, float d) {
    unsigned long long g;
    asm("cvta.to.global.u64 %0, %1;" : "=l"(g) : "l"(p));
    asm volatile("red.global.add.v4.f32 [%0], {%1, %2, %3, %4};"
                 :: "l"(g), "f"(a), "f"(b), "f"(c), "f"(d) : "memory");
}

// ---------------- edge aggregation: D=128, one warp per edge ---------------
__global__ void edge_agg128() {
    long long t = (long long)blockIdx.x * blockDim.x + threadIdx.x;
    int e = (int)(t >> 5);
    if (e >= E_EDGES) return;
    int lane = (int)(t & 31);
    int s = g_src[e];
    int d = g_dst[e];
    float nrm = g_norm[e];
    float4 v = ((const float4*)(g_h1 + (size_t)s * D_H1))[lane];
    float* out = g_msg1 + (size_t)d * D_H1 + lane * 4;
    red_v4(out, v.x * nrm, v.y * nrm, v.z * nrm, v.w * nrm);
}

// ---------------- edge aggregation: D=64, 16 threads per edge --------------
__global__ void edge_agg64() {
    long long t = (long long)blockIdx.x * blockDim.x + threadIdx.x;
    int e = (int)(t >> 4);
    if (e >= E_EDGES) return;
    int lane = (int)(t & 15);
    int s = g_src[e];
    int d = g_dst[e];
    float nrm = g_norm[e];
    float4 v = ((const float4*)(g_h2 + (size_t)s * D_H2))[lane];
    float* out = g_msg2 + (size_t)d * D_H2 + lane * 4;
    red_v4(out, v.x * nrm, v.y * nrm, v.z * nrm, v.w * nrm);
}

// ---------------- self-loop + bias + relu body ------------------------------
__device__ __forceinline__ void self_relu_body(float* h, const float* msg,
                                               const float* __restrict__ b, int D) {
    int i = blockIdx.x * blockDim.x + threadIdx.x;
    int d4 = D / 4;
    int total = N_NODES * d4;
    if (i >= total) return;
    int node = i / d4;
    int c4 = i - node * d4;
    float di = g_dinv[node];
    float d2 = di * di;
    float4 hv = ((const float4*)h)[i];
    float4 mv = ((const float4*)msg)[i];
    float4 bv = ((const float4*)b)[c4];
    float4 o;
    o.x = fmaxf(mv.x + d2 * hv.x + bv.x, 0.f);
    o.y = fmaxf(mv.y + d2 * hv.y + bv.y, 0.f);
    o.z = fmaxf(mv.z + d2 * hv.z + bv.z, 0.f);
    o.w = fmaxf(mv.w + d2 * hv.w + bv.w, 0.f);
    ((float4*)h)[i] = o;
}

__global__ void self_relu1(const float* __restrict__ b1) {
    self_relu_body(g_h1, g_msg1, b1, D_H1);
}
__global__ void self_relu2(const float* __restrict__ b2) {
    self_relu_body(g_h2, g_msg2, b2, D_H2);
}

// ---------------- launch ----------------------------------------------------
extern "C" void kernel_launch(void* const* d_in, const int* in_sizes, int n_in,
                              void* d_out, int out_size) {
    // Dispatch inputs by unique element count — immune to metadata ordering.
    const float *x = 0, *ew = 0, *W1 = 0, *b1 = 0, *W2 = 0, *b2 = 0, *Wc = 0, *bc = 0;
    const void* ei = 0;
    for (int i = 0; i < n_in; i++) {
        switch (in_sizes[i]) {
            case N_NODES * D_IN:   x  = (const float*)d_in[i]; break;
            case 2 * E_EDGES:      ei = d_in[i];               break;
            case E_EDGES:          ew = (const float*)d_in[i]; break;
            case D_IN * D_H1:      W1 = (const float*)d_in[i]; break;
            case D_H1:             b1 = (const float*)d_in[i]; break;
            case D_H1 * D_H2:      W2 = (const float*)d_in[i]; break;
            case D_H2:             b2 = (const float*)d_in[i]; break;
            case D_H2 * N_CLS:     Wc = (const float*)d_in[i]; break;
            case N_CLS:            bc = (const float*)d_in[i]; break;
            default: break;
        }
    }
    float* out = (float*)d_out;
    const int T = 256;

    detect_kernel<<<1, 256>>>((const unsigned int*)ei);
    convert_idx<<<(E_EDGES + T - 1) / T, T>>>(ei);

    {
        int n = N_NODES * D_H1 / 4;
        zero_bufs<<<(n + T - 1) / T, T>>>();
    }

    deg_kernel<<<(E_EDGES + T - 1) / T, T>>>(ew);
    dinv_kernel<<<(N_NODES + T - 1) / T, T>>>();
    norm_kernel<<<(E_EDGES + T - 1) / T, T>>>(ew);

    // layer 1
    {
        dim3 grid((N_NODES + 63) / 64, (D_H1 + 63) / 64);
        gemm_l1<<<grid, T>>>(x, W1);
    }
    {
        long long threads = (long long)E_EDGES * 32;
        edge_agg128<<<(unsigned)((threads + T - 1) / T), T>>>();
    }
    self_relu1<<<(N_NODES * D_H1 / 4 + T - 1) / T, T>>>(b1);

    // layer 2
    {
        dim3 grid((N_NODES + 63) / 64, (D_H2 + 63) / 64);
        gemm_l2<<<grid, T>>>(W2);
    }
    {
        long long threads = (long long)E_EDGES * 16;
        edge_agg64<<<(unsigned)((threads + T - 1) / T), T>>>();
    }
    self_relu2<<<(N_NODES * D_H2 / 4 + T - 1) / T, T>>>(b2);

    // classifier
    {
        dim3 grid((N_NODES + 63) / 64, (N_CLS + 63) / 64);
        gemm_l3<<<grid, T>>>(Wc, bc, out);
    }
}

// round 7
// speedup vs baseline: 1.0351x; 1.0351x over previous
#include <cuda_runtime.h>

#define N_NODES 100000
#define E_EDGES 1600000
#define D_IN  256
#define D_H1  128
#define D_H2  64
#define N_CLS 40

// ---------------- scratch (device globals; referenced ONLY in device code) --
__device__ int g_is64;
__device__ __align__(16) int   g_src[E_EDGES];
__device__ __align__(16) int   g_dst[E_EDGES];
__device__ __align__(16) float g_deg[N_NODES];          // accumulated edge weight
__device__ __align__(16) float g_norm[E_EDGES];
__device__ __align__(16) float g_h1[N_NODES * D_H1];
__device__ __align__(16) float g_msg1[N_NODES * D_H1];
__device__ __align__(16) float g_h2[N_NODES * D_H2];
__device__ __align__(16) float g_msg2[N_NODES * D_H2];

// ---------------- dtype detection ------------------------------------------
__global__ void detect_kernel(const unsigned int* __restrict__ ei_raw) {
    __shared__ int any_nonzero;
    if (threadIdx.x == 0) any_nonzero = 0;
    __syncthreads();
    int nz = 0;
    for (int k = threadIdx.x; k < 1024; k += blockDim.x)
        nz |= (ei_raw[2 * k + 1] != 0u);
    if (nz) atomicOr(&any_nonzero, 1);
    __syncthreads();
    if (threadIdx.x == 0) g_is64 = (any_nonzero == 0) ? 1 : 0;
}

// ---------------- zero accumulators (before convert_deg!) ------------------
__global__ void zero_bufs() {
    int i = blockIdx.x * blockDim.x + threadIdx.x;
    const int n1 = N_NODES * D_H1 / 4;
    const int n2 = N_NODES * D_H2 / 4;
    float4 z = make_float4(0.f, 0.f, 0.f, 0.f);
    if (i < n1) ((float4*)g_msg1)[i] = z;
    if (i < n2) ((float4*)g_msg2)[i] = z;
    if (i < N_NODES) g_deg[i] = 0.f;
}

// ---------------- decode indices + degree accumulation (fused) -------------
__global__ void convert_deg(const void* __restrict__ ei_raw,
                            const float* __restrict__ ew) {
    int e = blockIdx.x * blockDim.x + threadIdx.x;
    if (e >= E_EDGES) return;
    int s, d;
    if (g_is64) {
        const long long* p = (const long long*)ei_raw;
        s = (int)p[e];
        d = (int)p[E_EDGES + e];
    } else {
        const int* p = (const int*)ei_raw;
        s = p[e];
        d = p[E_EDGES + e];
    }
    g_src[e] = s;
    g_dst[e] = d;
    atomicAdd(&g_deg[d], ew[e]);
}

// ---------------- per-edge norm (rsqrt folded in) ---------------------------
__global__ void norm_kernel(const float* __restrict__ ew) {
    int e = blockIdx.x * blockDim.x + threadIdx.x;
    if (e < E_EDGES)
        g_norm[e] = rsqrtf(g_deg[g_src[e]] + 1.0f) * ew[e] *
                    rsqrtf(g_deg[g_dst[e]] + 1.0f);
}

// ---------------- high-throughput tiled fp32 GEMM ---------------------------
// C[M,Nc] = A[M,K] @ W[K,Nc]. 256 threads. BN must divide Nc, BK divide K.
template<int BM, int BN, int BK, int TM, int TN>
__device__ __forceinline__ void gemm_tile(const float* __restrict__ A,
                                          const float* __restrict__ W,
                                          float* __restrict__ C,
                                          int M, int K, int Nc) {
    __shared__ float As[BK][BM];
    __shared__ float Ws[BK][BN];
    const int NT = 256;
    const int tid = threadIdx.x;
    const int bm = blockIdx.x * BM;
    const int bn = blockIdx.y * BN;
    const int TX = BN / TN;
    const int tx = tid % TX;
    const int ty = tid / TX;

    float acc[TM][TN];
#pragma unroll
    for (int i = 0; i < TM; i++)
#pragma unroll
        for (int j = 0; j < TN; j++) acc[i][j] = 0.f;

    for (int kt = 0; kt < K; kt += BK) {
#pragma unroll
        for (int i = 0; i < (BM * BK / 4) / NT; i++) {
            int id = tid + i * NT;
            int ar = id / (BK / 4);
            int ac = (id % (BK / 4)) * 4;
            int row = bm + ar;
            float4 a = (row < M)
                ? *(const float4*)(A + (size_t)row * K + kt + ac)
                : make_float4(0.f, 0.f, 0.f, 0.f);
            As[ac + 0][ar] = a.x;
            As[ac + 1][ar] = a.y;
            As[ac + 2][ar] = a.z;
            As[ac + 3][ar] = a.w;
        }
#pragma unroll
        for (int i = 0; i < (BK * BN / 4) / NT; i++) {
            int id = tid + i * NT;
            int wr = id / (BN / 4);
            int wc = (id % (BN / 4)) * 4;
            *(float4*)&Ws[wr][wc] =
                *(const float4*)(W + (size_t)(kt + wr) * Nc + bn + wc);
        }
        __syncthreads();

#pragma unroll
        for (int k = 0; k < BK; k++) {
            float ra[TM], rb[TN];
#pragma unroll
            for (int i = 0; i < TM; i += 4)
                *(float4*)&ra[i] = *(const float4*)&As[k][ty * TM + i];
#pragma unroll
            for (int j = 0; j < TN; j += 4)
                *(float4*)&rb[j] = *(const float4*)&Ws[k][tx * TN + j];
#pragma unroll
            for (int i = 0; i < TM; i++)
#pragma unroll
                for (int j = 0; j < TN; j++) acc[i][j] += ra[i] * rb[j];
        }
        __syncthreads();
    }

#pragma unroll
    for (int i = 0; i < TM; i++) {
        int row = bm + ty * TM + i;
        if (row < M) {
#pragma unroll
            for (int j = 0; j < TN; j += 4) {
                float4 v = make_float4(acc[i][j], acc[i][j + 1],
                                       acc[i][j + 2], acc[i][j + 3]);
                *(float4*)(C + (size_t)row * Nc + bn + tx * TN + j) = v;
            }
        }
    }
}

__global__ void gemm_l1(const float* __restrict__ x, const float* __restrict__ W1) {
    gemm_tile<128, 128, 16, 8, 8>(x, W1, g_h1, N_NODES, D_IN, D_H1);
}
__global__ void gemm_l2(const float* __restrict__ W2) {
    gemm_tile<128, 64, 16, 8, 4>(g_h1, W2, g_h2, N_NODES, D_H1, D_H2);
}

// small classifier GEMM (0.5 GF): simple 64x64 kernel with bias + bounds
__global__ void gemm_l3(const float* __restrict__ Wc, const float* __restrict__ bc,
                        float* __restrict__ C) {
    const int M = N_NODES, K = D_H2, Nc = N_CLS;
    __shared__ float As[16][64];
    __shared__ float Ws[16][64];
    const float* A = g_h2;
    const int tid = threadIdx.x;
    const int bm = blockIdx.x * 64;
    const int bn = blockIdx.y * 64;
    const int ty = tid >> 4;
    const int tx = tid & 15;
    float acc[4][4];
#pragma unroll
    for (int i = 0; i < 4; i++)
#pragma unroll
        for (int j = 0; j < 4; j++) acc[i][j] = 0.f;

    for (int kt = 0; kt < K; kt += 16) {
        {
            int ar = tid >> 2;
            int ac = (tid & 3) * 4;
            int row = bm + ar;
            float4 a = (row < M)
                ? *(const float4*)(A + (size_t)row * K + kt + ac)
                : make_float4(0.f, 0.f, 0.f, 0.f);
            As[ac + 0][ar] = a.x;
            As[ac + 1][ar] = a.y;
            As[ac + 2][ar] = a.z;
            As[ac + 3][ar] = a.w;
        }
        {
            int wr = tid >> 4;
            int wc = (tid & 15) * 4;
            float4 w = make_float4(0.f, 0.f, 0.f, 0.f);
            if (bn + wc < Nc)
                w = *(const float4*)(Wc + (size_t)(kt + wr) * Nc + bn + wc);
            Ws[wr][wc + 0] = w.x;
            Ws[wr][wc + 1] = w.y;
            Ws[wr][wc + 2] = w.z;
            Ws[wr][wc + 3] = w.w;
        }
        __syncthreads();
#pragma unroll
        for (int k = 0; k < 16; k++) {
            float ra[4], rb[4];
#pragma unroll
            for (int i = 0; i < 4; i++) ra[i] = As[k][ty * 4 + i];
#pragma unroll
            for (int j = 0; j < 4; j++) rb[j] = Ws[k][tx * 4 + j];
#pragma unroll
            for (int i = 0; i < 4; i++)
#pragma unroll
                for (int j = 0; j < 4; j++) acc[i][j] += ra[i] * rb[j];
        }
        __syncthreads();
    }
#pragma unroll
    for (int i = 0; i < 4; i++) {
        int row = bm + ty * 4 + i;
        if (row >= M) continue;
#pragma unroll
        for (int j = 0; j < 4; j++) {
            int col = bn + tx * 4 + j;
            if (col < Nc)
                C[(size_t)row * Nc + col] = acc[i][j] + bc[col];
        }
    }
}

// ---------------- vector reduction helper -----------------------------------
__device__ __forceinline__ void red_v4(float* p, float a, float b, float c, float d) {
    unsigned long long g;
    asm("cvta.to.global.u64 %0, %1;" : "=l"(g) : "l"(p));
    asm volatile("red.global.add.v4.f32 [%0], {%1, %2, %3, %4};"
                 :: "l"(g), "f"(a), "f"(b), "f"(c), "f"(d) : "memory");
}

// ---------------- edge aggregation: D=128, one warp per edge ---------------
__global__ void edge_agg128() {
    long long t = (long long)blockIdx.x * blockDim.x + threadIdx.x;
    int e = (int)(t >> 5);
    if (e >= E_EDGES) return;
    int lane = (int)(t & 31);
    int s = g_src[e];
    int d = g_dst[e];
    float nrm = g_norm[e];
    float4 v = ((const float4*)(g_h1 + (size_t)s * D_H1))[lane];
    float* out = g_msg1 + (size_t)d * D_H1 + lane * 4;
    red_v4(out, v.x * nrm, v.y * nrm, v.z * nrm, v.w * nrm);
}

// ---------------- edge aggregation: D=64, 16 threads per edge --------------
__global__ void edge_agg64() {
    long long t = (long long)blockIdx.x * blockDim.x + threadIdx.x;
    int e = (int)(t >> 4);
    if (e >= E_EDGES) return;
    int lane = (int)(t & 15);
    int s = g_src[e];
    int d = g_dst[e];
    float nrm = g_norm[e];
    float4 v = ((const float4*)(g_h2 + (size_t)s * D_H2))[lane];
    float* out = g_msg2 + (size_t)d * D_H2 + lane * 4;
    red_v4(out, v.x * nrm, v.y * nrm, v.z * nrm, v.w * nrm);
}

// ---------------- self-loop + bias + relu -----------------------------------
__device__ __forceinline__ void self_relu_body(float* h, const float* msg,
                                               const float* __restrict__ b, int D) {
    int i = blockIdx.x * blockDim.x + threadIdx.x;
    int d4 = D / 4;
    int total = N_NODES * d4;
    if (i >= total) return;
    int node = i / d4;
    int c4 = i - node * d4;
    float di = rsqrtf(g_deg[node] + 1.0f);
    float d2 = di * di;
    float4 hv = ((const float4*)h)[i];
    float4 mv = ((const float4*)msg)[i];
    float4 bv = ((const float4*)b)[c4];
    float4 o;
    o.x = fmaxf(mv.x + d2 * hv.x + bv.x, 0.f);
    o.y = fmaxf(mv.y + d2 * hv.y + bv.y, 0.f);
    o.z = fmaxf(mv.z + d2 * hv.z + bv.z, 0.f);
    o.w = fmaxf(mv.w + d2 * hv.w + bv.w, 0.f);
    ((float4*)h)[i] = o;
}

__global__ void self_relu1(const float* __restrict__ b1) {
    self_relu_body(g_h1, g_msg1, b1, D_H1);
}
__global__ void self_relu2(const float* __restrict__ b2) {
    self_relu_body(g_h2, g_msg2, b2, D_H2);
}

// ---------------- launch ----------------------------------------------------
extern "C" void kernel_launch(void* const* d_in, const int* in_sizes, int n_in,
                              void* d_out, int out_size) {
    const float *x = 0, *ew = 0, *W1 = 0, *b1 = 0, *W2 = 0, *b2 = 0, *Wc = 0, *bc = 0;
    const void* ei = 0;
    for (int i = 0; i < n_in; i++) {
        switch (in_sizes[i]) {
            case N_NODES * D_IN:   x  = (const float*)d_in[i]; break;
            case 2 * E_EDGES:      ei = d_in[i];               break;
            case E_EDGES:          ew = (const float*)d_in[i]; break;
            case D_IN * D_H1:      W1 = (const float*)d_in[i]; break;
            case D_H1:             b1 = (const float*)d_in[i]; break;
            case D_H1 * D_H2:      W2 = (const float*)d_in[i]; break;
            case D_H2:             b2 = (const float*)d_in[i]; break;
            case D_H2 * N_CLS:     Wc = (const float*)d_in[i]; break;
            case N_CLS:            bc = (const float*)d_in[i]; break;
            default: break;
        }
    }
    float* out = (float*)d_out;
    const int T = 256;

    // launch order chosen so ncu (-s 5 -c 1) captures edge_agg128 (launch #6)
    detect_kernel<<<1, 256>>>((const unsigned int*)ei);                       // 1
    {
        int n = N_NODES * D_H1 / 4;
        zero_bufs<<<(n + T - 1) / T, T>>>();                                  // 2
    }
    convert_deg<<<(E_EDGES + T - 1) / T, T>>>(ei, ew);                        // 3
    norm_kernel<<<(E_EDGES + T - 1) / T, T>>>(ew);                            // 4

    gemm_l1<<<dim3((N_NODES + 127) / 128, 1), T>>>(x, W1);                    // 5
    {
        long long threads = (long long)E_EDGES * 32;
        edge_agg128<<<(unsigned)((threads + T - 1) / T), T>>>();              // 6
    }
    self_relu1<<<(N_NODES * D_H1 / 4 + T - 1) / T, T>>>(b1);                  // 7

    gemm_l2<<<dim3((N_NODES + 127) / 128, 1), T>>>(W2);                       // 8
    {
        long long threads = (long long)E_EDGES * 16;
        edge_agg64<<<(unsigned)((threads + T - 1) / T), T>>>();               // 9
    }
    self_relu2<<<(N_NODES * D_H2 / 4 + T - 1) / T, T>>>(b2);                  // 10

    gemm_l3<<<dim3((N_NODES + 63) / 64, 1), T>>>(Wc, bc, out);                // 11
}

// round 8
// speedup vs baseline: 1.0980x; 1.0608x over previous
#include <cuda_runtime.h>

#define N_NODES 100000
#define E_EDGES 1600000
#define D_IN  256
#define D_H1  128
#define D_H2  64
#define N_CLS 40

// ---------------- scratch (device globals; referenced ONLY in device code) --
__device__ int g_is64;
__device__ __align__(16) int   g_src[E_EDGES];
__device__ __align__(16) int   g_dst[E_EDGES];
__device__ __align__(16) float g_deg[N_NODES];       // sum of incoming edge weights
__device__ __align__(16) int   g_cnt[N_NODES];       // in-degree counts
__device__ __align__(16) int   g_rowptr[N_NODES + 1];
__device__ __align__(16) int   g_cursor[N_NODES];
__device__ __align__(16) int   g_csr_src[E_EDGES];   // src sorted by dst
__device__ __align__(16) float g_csr_w[E_EDGES];     // norm sorted by dst
__device__ __align__(16) float g_h1[N_NODES * D_H1]; // x@W1
__device__ __align__(16) float g_a1[N_NODES * D_H1]; // relu(conv1)
__device__ __align__(16) float g_h2[N_NODES * D_H2]; // a1@W2
__device__ __align__(16) float g_a2[N_NODES * D_H2]; // relu(conv2)

// ---------------- dtype detection ------------------------------------------
__global__ void detect_kernel(const unsigned int* __restrict__ ei_raw) {
    __shared__ int any_nonzero;
    if (threadIdx.x == 0) any_nonzero = 0;
    __syncthreads();
    int nz = 0;
    for (int k = threadIdx.x; k < 1024; k += blockDim.x)
        nz |= (ei_raw[2 * k + 1] != 0u);
    if (nz) atomicOr(&any_nonzero, 1);
    __syncthreads();
    if (threadIdx.x == 0) g_is64 = (any_nonzero == 0) ? 1 : 0;
}

// ---------------- zero counters ---------------------------------------------
__global__ void zero_bufs() {
    int i = blockIdx.x * blockDim.x + threadIdx.x;
    if (i < N_NODES) { g_deg[i] = 0.f; g_cnt[i] = 0; }
}

// ---------------- decode indices + degree (float) + count (int) ------------
__global__ void convert_deg(const void* __restrict__ ei_raw,
                            const float* __restrict__ ew) {
    int e = blockIdx.x * blockDim.x + threadIdx.x;
    if (e >= E_EDGES) return;
    int s, d;
    if (g_is64) {
        const long long* p = (const long long*)ei_raw;
        s = (int)p[e];
        d = (int)p[E_EDGES + e];
    } else {
        const int* p = (const int*)ei_raw;
        s = p[e];
        d = p[E_EDGES + e];
    }
    g_src[e] = s;
    g_dst[e] = d;
    atomicAdd(&g_deg[d], ew[e]);
    atomicAdd(&g_cnt[d], 1);
}

// ---------------- exclusive prefix sum over counts (single block) ----------
__global__ void scan_kernel() {
    const int T = 1024;
    const int CH = (N_NODES + T - 1) / T;  // 98
    int tid = threadIdx.x;
    int base = tid * CH;
    int sum = 0;
    for (int i = 0; i < CH; i++) {
        int idx = base + i;
        if (idx < N_NODES) sum += g_cnt[idx];
    }
    __shared__ int ssum[T];
    ssum[tid] = sum;
    __syncthreads();
    // Hillis-Steele inclusive scan
    for (int off = 1; off < T; off *= 2) {
        int v = (tid >= off) ? ssum[tid - off] : 0;
        __syncthreads();
        ssum[tid] += v;
        __syncthreads();
    }
    int run = (tid == 0) ? 0 : ssum[tid - 1];
    for (int i = 0; i < CH; i++) {
        int idx = base + i;
        if (idx < N_NODES) {
            g_rowptr[idx] = run;
            g_cursor[idx] = run;
            run += g_cnt[idx];
        }
    }
    if (tid == T - 1) g_rowptr[N_NODES] = run;
}

// ---------------- scatter edges into CSR, norm computed inline -------------
__global__ void scatter_kernel(const float* __restrict__ ew) {
    int e = blockIdx.x * blockDim.x + threadIdx.x;
    if (e >= E_EDGES) return;
    int s = g_src[e];
    int d = g_dst[e];
    float nrm = rsqrtf(g_deg[s] + 1.0f) * ew[e] * rsqrtf(g_deg[d] + 1.0f);
    int pos = atomicAdd(&g_cursor[d], 1);
    g_csr_src[pos] = s;
    g_csr_w[pos] = nrm;
}

// ---------------- high-throughput tiled fp32 GEMM ---------------------------
template<int BM, int BN, int BK, int TM, int TN>
__device__ __forceinline__ void gemm_tile(const float* __restrict__ A,
                                          const float* __restrict__ W,
                                          float* __restrict__ C,
                                          int M, int K, int Nc) {
    __shared__ float As[BK][BM];
    __shared__ float Ws[BK][BN];
    const int NT = 256;
    const int tid = threadIdx.x;
    const int bm = blockIdx.x * BM;
    const int bn = blockIdx.y * BN;
    const int TX = BN / TN;
    const int tx = tid % TX;
    const int ty = tid / TX;

    float acc[TM][TN];
#pragma unroll
    for (int i = 0; i < TM; i++)
#pragma unroll
        for (int j = 0; j < TN; j++) acc[i][j] = 0.f;

    for (int kt = 0; kt < K; kt += BK) {
#pragma unroll
        for (int i = 0; i < (BM * BK / 4) / NT; i++) {
            int id = tid + i * NT;
            int ar = id / (BK / 4);
            int ac = (id % (BK / 4)) * 4;
            int row = bm + ar;
            float4 a = (row < M)
                ? *(const float4*)(A + (size_t)row * K + kt + ac)
                : make_float4(0.f, 0.f, 0.f, 0.f);
            As[ac + 0][ar] = a.x;
            As[ac + 1][ar] = a.y;
            As[ac + 2][ar] = a.z;
            As[ac + 3][ar] = a.w;
        }
#pragma unroll
        for (int i = 0; i < (BK * BN / 4) / NT; i++) {
            int id = tid + i * NT;
            int wr = id / (BN / 4);
            int wc = (id % (BN / 4)) * 4;
            *(float4*)&Ws[wr][wc] =
                *(const float4*)(W + (size_t)(kt + wr) * Nc + bn + wc);
        }
        __syncthreads();

#pragma unroll
        for (int k = 0; k < BK; k++) {
            float ra[TM], rb[TN];
#pragma unroll
            for (int i = 0; i < TM; i += 4)
                *(float4*)&ra[i] = *(const float4*)&As[k][ty * TM + i];
#pragma unroll
            for (int j = 0; j < TN; j += 4)
                *(float4*)&rb[j] = *(const float4*)&Ws[k][tx * TN + j];
#pragma unroll
            for (int i = 0; i < TM; i++)
#pragma unroll
                for (int j = 0; j < TN; j++) acc[i][j] += ra[i] * rb[j];
        }
        __syncthreads();
    }

#pragma unroll
    for (int i = 0; i < TM; i++) {
        int row = bm + ty * TM + i;
        if (row < M) {
#pragma unroll
            for (int j = 0; j < TN; j += 4) {
                float4 v = make_float4(acc[i][j], acc[i][j + 1],
                                       acc[i][j + 2], acc[i][j + 3]);
                *(float4*)(C + (size_t)row * Nc + bn + tx * TN + j) = v;
            }
        }
    }
}

__global__ void gemm_l1(const float* __restrict__ x, const float* __restrict__ W1) {
    gemm_tile<128, 128, 16, 8, 8>(x, W1, g_h1, N_NODES, D_IN, D_H1);
}
__global__ void gemm_l2(const float* __restrict__ W2) {
    gemm_tile<128, 64, 16, 8, 4>(g_a1, W2, g_h2, N_NODES, D_H1, D_H2);
}

// small classifier GEMM with bias
__global__ void gemm_l3(const float* __restrict__ Wc, const float* __restrict__ bc,
                        float* __restrict__ C) {
    const int M = N_NODES, K = D_H2, Nc = N_CLS;
    __shared__ float As[16][64];
    __shared__ float Ws[16][64];
    const float* A = g_a2;
    const int tid = threadIdx.x;
    const int bm = blockIdx.x * 64;
    const int bn = blockIdx.y * 64;
    const int ty = tid >> 4;
    const int tx = tid & 15;
    float acc[4][4];
#pragma unroll
    for (int i = 0; i < 4; i++)
#pragma unroll
        for (int j = 0; j < 4; j++) acc[i][j] = 0.f;

    for (int kt = 0; kt < K; kt += 16) {
        {
            int ar = tid >> 2;
            int ac = (tid & 3) * 4;
            int row = bm + ar;
            float4 a = (row < M)
                ? *(const float4*)(A + (size_t)row * K + kt + ac)
                : make_float4(0.f, 0.f, 0.f, 0.f);
            As[ac + 0][ar] = a.x;
            As[ac + 1][ar] = a.y;
            As[ac + 2][ar] = a.z;
            As[ac + 3][ar] = a.w;
        }
        {
            int wr = tid >> 4;
            int wc = (tid & 15) * 4;
            float4 w = make_float4(0.f, 0.f, 0.f, 0.f);
            if (bn + wc < Nc)
                w = *(const float4*)(Wc + (size_t)(kt + wr) * Nc + bn + wc);
            Ws[wr][wc + 0] = w.x;
            Ws[wr][wc + 1] = w.y;
            Ws[wr][wc + 2] = w.z;
            Ws[wr][wc + 3] = w.w;
        }
        __syncthreads();
#pragma unroll
        for (int k = 0; k < 16; k++) {
            float ra[4], rb[4];
#pragma unroll
            for (int i = 0; i < 4; i++) ra[i] = As[k][ty * 4 + i];
#pragma unroll
            for (int j = 0; j < 4; j++) rb[j] = Ws[k][tx * 4 + j];
#pragma unroll
            for (int i = 0; i < 4; i++)
#pragma unroll
                for (int j = 0; j < 4; j++) acc[i][j] += ra[i] * rb[j];
        }
        __syncthreads();
    }
#pragma unroll
    for (int i = 0; i < 4; i++) {
        int row = bm + ty * 4 + i;
        if (row >= M) continue;
#pragma unroll
        for (int j = 0; j < 4; j++) {
            int col = bn + tx * 4 + j;
            if (col < Nc)
                C[(size_t)row * Nc + col] = acc[i][j] + bc[col];
        }
    }
}

// ---------------- pull aggregation, layer 1 (D=128, warp per node) ---------
// a1[d] = relu( sum_in w*h1[src] + dinv^2*h1[d] + b1 )
__global__ void agg1(const float* __restrict__ b1) {
    int node = (blockIdx.x * blockDim.x + threadIdx.x) >> 5;
    if (node >= N_NODES) return;
    int lane = threadIdx.x & 31;
    int start = g_rowptr[node];
    int end = g_rowptr[node + 1];
    float4 acc = make_float4(0.f, 0.f, 0.f, 0.f);
    for (int j = start; j < end; j++) {
        int s = g_csr_src[j];
        float w = g_csr_w[j];
        float4 v = ((const float4*)(g_h1 + (size_t)s * D_H1))[lane];
        acc.x += w * v.x;
        acc.y += w * v.y;
        acc.z += w * v.z;
        acc.w += w * v.w;
    }
    float dv = rsqrtf(g_deg[node] + 1.0f);
    float d2 = dv * dv;
    float4 hv = ((const float4*)(g_h1 + (size_t)node * D_H1))[lane];
    float4 bv = ((const float4*)b1)[lane];
    float4 o;
    o.x = fmaxf(acc.x + d2 * hv.x + bv.x, 0.f);
    o.y = fmaxf(acc.y + d2 * hv.y + bv.y, 0.f);
    o.z = fmaxf(acc.z + d2 * hv.z + bv.z, 0.f);
    o.w = fmaxf(acc.w + d2 * hv.w + bv.w, 0.f);
    ((float4*)(g_a1 + (size_t)node * D_H1))[lane] = o;
}

// ---------------- pull aggregation, layer 2 (D=64, half-warp per node) -----
__global__ void agg2(const float* __restrict__ b2) {
    int t = blockIdx.x * blockDim.x + threadIdx.x;
    int node = t >> 4;
    if (node >= N_NODES) return;
    int lane = t & 15;
    int start = g_rowptr[node];
    int end = g_rowptr[node + 1];
    float4 acc = make_float4(0.f, 0.f, 0.f, 0.f);
    for (int j = start; j < end; j++) {
        int s = g_csr_src[j];
        float w = g_csr_w[j];
        float4 v = ((const float4*)(g_h2 + (size_t)s * D_H2))[lane];
        acc.x += w * v.x;
        acc.y += w * v.y;
        acc.z += w * v.z;
        acc.w += w * v.w;
    }
    float dv = rsqrtf(g_deg[node] + 1.0f);
    float d2 = dv * dv;
    float4 hv = ((const float4*)(g_h2 + (size_t)node * D_H2))[lane];
    float4 bv = ((const float4*)b2)[lane];
    float4 o;
    o.x = fmaxf(acc.x + d2 * hv.x + bv.x, 0.f);
    o.y = fmaxf(acc.y + d2 * hv.y + bv.y, 0.f);
    o.z = fmaxf(acc.z + d2 * hv.z + bv.z, 0.f);
    o.w = fmaxf(acc.w + d2 * hv.w + bv.w, 0.f);
    ((float4*)(g_a2 + (size_t)node * D_H2))[lane] = o;
}

// ---------------- launch ----------------------------------------------------
extern "C" void kernel_launch(void* const* d_in, const int* in_sizes, int n_in,
                              void* d_out, int out_size) {
    const float *x = 0, *ew = 0, *W1 = 0, *b1 = 0, *W2 = 0, *b2 = 0, *Wc = 0, *bc = 0;
    const void* ei = 0;
    for (int i = 0; i < n_in; i++) {
        switch (in_sizes[i]) {
            case N_NODES * D_IN:   x  = (const float*)d_in[i]; break;
            case 2 * E_EDGES:      ei = d_in[i];               break;
            case E_EDGES:          ew = (const float*)d_in[i]; break;
            case D_IN * D_H1:      W1 = (const float*)d_in[i]; break;
            case D_H1:             b1 = (const float*)d_in[i]; break;
            case D_H1 * D_H2:      W2 = (const float*)d_in[i]; break;
            case D_H2:             b2 = (const float*)d_in[i]; break;
            case D_H2 * N_CLS:     Wc = (const float*)d_in[i]; break;
            case N_CLS:            bc = (const float*)d_in[i]; break;
            default: break;
        }
    }
    float* out = (float*)d_out;
    const int T = 256;

    detect_kernel<<<1, 256>>>((const unsigned int*)ei);                 // 1
    zero_bufs<<<(N_NODES + T - 1) / T, T>>>();                          // 2
    convert_deg<<<(E_EDGES + T - 1) / T, T>>>(ei, ew);                  // 3
    gemm_l1<<<dim3((N_NODES + 127) / 128, 1), T>>>(x, W1);              // 4 (profiled)
    scan_kernel<<<1, 1024>>>();                                         // 5
    scatter_kernel<<<(E_EDGES + T - 1) / T, T>>>(ew);                   // 6
    agg1<<<(N_NODES * 32 + T - 1) / T, T>>>(b1);                        // 7
    gemm_l2<<<dim3((N_NODES + 127) / 128, 1), T>>>(W2);                 // 8
    agg2<<<(N_NODES * 16 + T - 1) / T, T>>>(b2);                        // 9
    gemm_l3<<<dim3((N_NODES + 63) / 64, 1), T>>>(Wc, bc, out);          // 10
}

// round 9
// speedup vs baseline: 1.1344x; 1.0332x over previous
#include <cuda_runtime.h>

#define N_NODES 100000
#define E_EDGES 1600000
#define D_IN  256
#define D_H1  128
#define D_H2  64
#define N_CLS 40

// ---------------- scratch (device globals; referenced ONLY in device code) --
__device__ int g_is64;
__device__ __align__(16) float g_deg[N_NODES];        // sum of incoming edge weights
__device__ __align__(16) int   g_cnt[N_NODES];        // in-degree counts
__device__ __align__(16) int   g_rowptr[N_NODES + 1];
__device__ __align__(16) int   g_cursor[N_NODES];
__device__ __align__(16) int2  g_csr[E_EDGES];        // (src, norm-bits) sorted by dst
__device__ __align__(16) float g_h1[N_NODES * D_H1];  // x@W1
__device__ __align__(16) float g_a1[N_NODES * D_H1];  // relu(conv1)
__device__ __align__(16) float g_h2[N_NODES * D_H2];  // a1@W2
__device__ __align__(16) float g_a2[N_NODES * D_H2];  // relu(conv2)

// ---------------- dtype detection ------------------------------------------
__global__ void detect_kernel(const unsigned int* __restrict__ ei_raw) {
    __shared__ int any_nonzero;
    if (threadIdx.x == 0) any_nonzero = 0;
    __syncthreads();
    int nz = 0;
    for (int k = threadIdx.x; k < 1024; k += blockDim.x)
        nz |= (ei_raw[2 * k + 1] != 0u);
    if (nz) atomicOr(&any_nonzero, 1);
    __syncthreads();
    if (threadIdx.x == 0) g_is64 = (any_nonzero == 0) ? 1 : 0;
}

// ---------------- zero counters ---------------------------------------------
__global__ void zero_bufs() {
    int i = blockIdx.x * blockDim.x + threadIdx.x;
    if (i < N_NODES) { g_deg[i] = 0.f; g_cnt[i] = 0; }
}

// ---------------- edge decode helper ----------------------------------------
__device__ __forceinline__ void decode_edge(const void* ei_raw, int e, int& s, int& d) {
    if (g_is64) {
        const long long* p = (const long long*)ei_raw;
        s = (int)p[e];
        d = (int)p[E_EDGES + e];
    } else {
        const int* p = (const int*)ei_raw;
        s = p[e];
        d = p[E_EDGES + e];
    }
}

// ---------------- degree (float) + count (int) ------------------------------
__global__ void convert_deg(const void* __restrict__ ei_raw,
                            const float* __restrict__ ew) {
    int e = blockIdx.x * blockDim.x + threadIdx.x;
    if (e >= E_EDGES) return;
    int s, d;
    decode_edge(ei_raw, e, s, d);
    atomicAdd(&g_deg[d], ew[e]);
    atomicAdd(&g_cnt[d], 1);
}

// ---------------- exclusive prefix sum over counts (single block) ----------
__global__ void scan_kernel() {
    const int T = 1024;
    const int CH = (N_NODES + T - 1) / T;  // 98
    int tid = threadIdx.x;
    int base = tid * CH;
    int sum = 0;
    for (int i = 0; i < CH; i++) {
        int idx = base + i;
        if (idx < N_NODES) sum += g_cnt[idx];
    }
    __shared__ int ssum[T];
    ssum[tid] = sum;
    __syncthreads();
    for (int off = 1; off < T; off *= 2) {
        int v = (tid >= off) ? ssum[tid - off] : 0;
        __syncthreads();
        ssum[tid] += v;
        __syncthreads();
    }
    int run = (tid == 0) ? 0 : ssum[tid - 1];
    for (int i = 0; i < CH; i++) {
        int idx = base + i;
        if (idx < N_NODES) {
            g_rowptr[idx] = run;
            g_cursor[idx] = run;
            run += g_cnt[idx];
        }
    }
    if (tid == T - 1) g_rowptr[N_NODES] = run;
}

// ---------------- scatter edges into packed CSR -----------------------------
__global__ void scatter_kernel(const void* __restrict__ ei_raw,
                               const float* __restrict__ ew) {
    int e = blockIdx.x * blockDim.x + threadIdx.x;
    if (e >= E_EDGES) return;
    int s, d;
    decode_edge(ei_raw, e, s, d);
    float nrm = rsqrtf(g_deg[s] + 1.0f) * ew[e] * rsqrtf(g_deg[d] + 1.0f);
    int pos = atomicAdd(&g_cursor[d], 1);
    g_csr[pos] = make_int2(s, __float_as_int(nrm));
}

// ---------------- cp.async helpers ------------------------------------------
__device__ __forceinline__ void cp_async16(void* smem_dst, const void* gmem_src) {
    unsigned int sa = (unsigned int)__cvta_generic_to_shared(smem_dst);
    asm volatile("cp.async.cg.shared.global [%0], [%1], 16;"
                 :: "r"(sa), "l"(gmem_src) : "memory");
}
__device__ __forceinline__ void cp_async_commit() {
    asm volatile("cp.async.commit_group;" ::: "memory");
}
__device__ __forceinline__ void cp_async_wait0() {
    asm volatile("cp.async.wait_group 0;" ::: "memory");
}

// ---------------- double-buffered fp32 GEMM: C = A[M,K] @ W[K,Nc] ----------
// 256 threads. BN == Nc required (single block-column). K % BK == 0.
template<int BM, int BN, int BK, int TM, int TN>
__device__ __forceinline__ void gemm_db(const float* __restrict__ A,
                                        const float* __restrict__ W,
                                        float* __restrict__ C,
                                        int M, int K, int Nc) {
    __shared__ float As[2][BK][BM];
    __shared__ float Ws[2][BK][BN];
    const int NT = 256;
    const int A_LD = (BM * BK / 4) / NT;   // float4 loads per thread for A
    const int W_LD = (BK * BN / 4) / NT;   // float4 cp.asyncs per thread for W

    const int tid = threadIdx.x;
    const int bm = blockIdx.x * BM;
    const int TX = BN / TN;
    const int tx = tid % TX;
    const int ty = tid / TX;

    float acc[TM][TN];
#pragma unroll
    for (int i = 0; i < TM; i++)
#pragma unroll
        for (int j = 0; j < TN; j++) acc[i][j] = 0.f;

    float4 aReg[A_LD];

    // --- A tile: global -> regs (bounds-checked) ---
    auto loadA = [&](int kt) {
#pragma unroll
        for (int i = 0; i < A_LD; i++) {
            int id = tid + i * NT;
            int ar = id / (BK / 4);
            int ac = (id % (BK / 4)) * 4;
            int row = bm + ar;
            aReg[i] = (row < M)
                ? *(const float4*)(A + (size_t)row * K + kt + ac)
                : make_float4(0.f, 0.f, 0.f, 0.f);
        }
    };
    // --- A tile: regs -> smem (transposed to [k][m]) ---
    auto storeA = [&](int buf) {
#pragma unroll
        for (int i = 0; i < A_LD; i++) {
            int id = tid + i * NT;
            int ar = id / (BK / 4);
            int ac = (id % (BK / 4)) * 4;
            As[buf][ac + 0][ar] = aReg[i].x;
            As[buf][ac + 1][ar] = aReg[i].y;
            As[buf][ac + 2][ar] = aReg[i].z;
            As[buf][ac + 3][ar] = aReg[i].w;
        }
    };
    // --- W tile: global -> smem via cp.async (no bounds needed) ---
    auto loadW = [&](int kt, int buf) {
#pragma unroll
        for (int i = 0; i < W_LD; i++) {
            int id = tid + i * NT;
            int wr = id / (BN / 4);
            int wc = (id % (BN / 4)) * 4;
            cp_async16(&Ws[buf][wr][wc], W + (size_t)(kt + wr) * Nc + wc);
        }
    };

    // prologue: tile 0 into buffer 0
    loadA(0);
    storeA(0);
    loadW(0, 0);
    cp_async_commit();
    cp_async_wait0();
    __syncthreads();

    const int nIter = K / BK;
    for (int it = 0; it < nIter; it++) {
        int buf = it & 1;
        int nxt = buf ^ 1;
        if (it + 1 < nIter) {
            loadW((it + 1) * BK, nxt);
            cp_async_commit();
            loadA((it + 1) * BK);
        }
#pragma unroll
        for (int k = 0; k < BK; k++) {
            float ra[TM], rb[TN];
#pragma unroll
            for (int i = 0; i < TM; i += 4)
                *(float4*)&ra[i] = *(const float4*)&As[buf][k][ty * TM + i];
#pragma unroll
            for (int j = 0; j < TN; j += 4)
                *(float4*)&rb[j] = *(const float4*)&Ws[buf][k][tx * TN + j];
#pragma unroll
            for (int i = 0; i < TM; i++)
#pragma unroll
                for (int j = 0; j < TN; j++) acc[i][j] += ra[i] * rb[j];
        }
        if (it + 1 < nIter) {
            storeA(nxt);
            cp_async_wait0();
            __syncthreads();
        }
    }

#pragma unroll
    for (int i = 0; i < TM; i++) {
        int row = bm + ty * TM + i;
        if (row < M) {
#pragma unroll
            for (int j = 0; j < TN; j += 4) {
                float4 v = make_float4(acc[i][j], acc[i][j + 1],
                                       acc[i][j + 2], acc[i][j + 3]);
                *(float4*)(C + (size_t)row * Nc + tx * TN + j) = v;
            }
        }
    }
}

__global__ void __launch_bounds__(256) gemm_l1(const float* __restrict__ x,
                                               const float* __restrict__ W1) {
    gemm_db<128, 128, 16, 8, 8>(x, W1, g_h1, N_NODES, D_IN, D_H1);
}
__global__ void __launch_bounds__(256) gemm_l2(const float* __restrict__ W2) {
    gemm_db<128, 64, 16, 8, 4>(g_a1, W2, g_h2, N_NODES, D_H1, D_H2);
}

// small classifier GEMM with bias (unchanged; ~cheap)
__global__ void gemm_l3(const float* __restrict__ Wc, const float* __restrict__ bc,
                        float* __restrict__ C) {
    const int M = N_NODES, K = D_H2, Nc = N_CLS;
    __shared__ float As[16][64];
    __shared__ float Ws[16][64];
    const float* A = g_a2;
    const int tid = threadIdx.x;
    const int bm = blockIdx.x * 64;
    const int bn = blockIdx.y * 64;
    const int ty = tid >> 4;
    const int tx = tid & 15;
    float acc[4][4];
#pragma unroll
    for (int i = 0; i < 4; i++)
#pragma unroll
        for (int j = 0; j < 4; j++) acc[i][j] = 0.f;

    for (int kt = 0; kt < K; kt += 16) {
        {
            int ar = tid >> 2;
            int ac = (tid & 3) * 4;
            int row = bm + ar;
            float4 a = (row < M)
                ? *(const float4*)(A + (size_t)row * K + kt + ac)
                : make_float4(0.f, 0.f, 0.f, 0.f);
            As[ac + 0][ar] = a.x;
            As[ac + 1][ar] = a.y;
            As[ac + 2][ar] = a.z;
            As[ac + 3][ar] = a.w;
        }
        {
            int wr = tid >> 4;
            int wc = (tid & 15) * 4;
            float4 w = make_float4(0.f, 0.f, 0.f, 0.f);
            if (bn + wc < Nc)
                w = *(const float4*)(Wc + (size_t)(kt + wr) * Nc + bn + wc);
            Ws[wr][wc + 0] = w.x;
            Ws[wr][wc + 1] = w.y;
            Ws[wr][wc + 2] = w.z;
            Ws[wr][wc + 3] = w.w;
        }
        __syncthreads();
#pragma unroll
        for (int k = 0; k < 16; k++) {
            float ra[4], rb[4];
#pragma unroll
            for (int i = 0; i < 4; i++) ra[i] = As[k][ty * 4 + i];
#pragma unroll
            for (int j = 0; j < 4; j++) rb[j] = Ws[k][tx * 4 + j];
#pragma unroll
            for (int i = 0; i < 4; i++)
#pragma unroll
                for (int j = 0; j < 4; j++) acc[i][j] += ra[i] * rb[j];
        }
        __syncthreads();
    }
#pragma unroll
    for (int i = 0; i < 4; i++) {
        int row = bm + ty * 4 + i;
        if (row >= M) continue;
#pragma unroll
        for (int j = 0; j < 4; j++) {
            int col = bn + tx * 4 + j;
            if (col < Nc)
                C[(size_t)row * Nc + col] = acc[i][j] + bc[col];
        }
    }
}

// ---------------- pull aggregation, layer 1 (D=128, warp per node) ---------
// a1[d] = relu( sum_in w*h1[src] + dinv^2*h1[d] + b1 ), 4x unrolled (MLP 4)
__global__ void agg1(const float* __restrict__ b1) {
    int node = (blockIdx.x * blockDim.x + threadIdx.x) >> 5;
    if (node >= N_NODES) return;
    int lane = threadIdx.x & 31;
    int j = g_rowptr[node];
    int end = g_rowptr[node + 1];
    float4 acc = make_float4(0.f, 0.f, 0.f, 0.f);

    for (; j + 4 <= end; j += 4) {
        int2 e0 = g_csr[j + 0];
        int2 e1 = g_csr[j + 1];
        int2 e2 = g_csr[j + 2];
        int2 e3 = g_csr[j + 3];
        float4 v0 = ((const float4*)(g_h1 + (size_t)e0.x * D_H1))[lane];
        float4 v1 = ((const float4*)(g_h1 + (size_t)e1.x * D_H1))[lane];
        float4 v2 = ((const float4*)(g_h1 + (size_t)e2.x * D_H1))[lane];
        float4 v3 = ((const float4*)(g_h1 + (size_t)e3.x * D_H1))[lane];
        float w0 = __int_as_float(e0.y);
        float w1 = __int_as_float(e1.y);
        float w2 = __int_as_float(e2.y);
        float w3 = __int_as_float(e3.y);
        acc.x += w0 * v0.x + w1 * v1.x + w2 * v2.x + w3 * v3.x;
        acc.y += w0 * v0.y + w1 * v1.y + w2 * v2.y + w3 * v3.y;
        acc.z += w0 * v0.z + w1 * v1.z + w2 * v2.z + w3 * v3.z;
        acc.w += w0 * v0.w + w1 * v1.w + w2 * v2.w + w3 * v3.w;
    }
    for (; j < end; j++) {
        int2 e = g_csr[j];
        float w = __int_as_float(e.y);
        float4 v = ((const float4*)(g_h1 + (size_t)e.x * D_H1))[lane];
        acc.x += w * v.x;
        acc.y += w * v.y;
        acc.z += w * v.z;
        acc.w += w * v.w;
    }
    float dv = rsqrtf(g_deg[node] + 1.0f);
    float d2 = dv * dv;
    float4 hv = ((const float4*)(g_h1 + (size_t)node * D_H1))[lane];
    float4 bv = ((const float4*)b1)[lane];
    float4 o;
    o.x = fmaxf(acc.x + d2 * hv.x + bv.x, 0.f);
    o.y = fmaxf(acc.y + d2 * hv.y + bv.y, 0.f);
    o.z = fmaxf(acc.z + d2 * hv.z + bv.z, 0.f);
    o.w = fmaxf(acc.w + d2 * hv.w + bv.w, 0.f);
    ((float4*)(g_a1 + (size_t)node * D_H1))[lane] = o;
}

// ---------------- pull aggregation, layer 2 (D=64, half-warp per node) -----
__global__ void agg2(const float* __restrict__ b2) {
    int t = blockIdx.x * blockDim.x + threadIdx.x;
    int node = t >> 4;
    if (node >= N_NODES) return;
    int lane = t & 15;
    int j = g_rowptr[node];
    int end = g_rowptr[node + 1];
    float4 acc = make_float4(0.f, 0.f, 0.f, 0.f);

    for (; j + 4 <= end; j += 4) {
        int2 e0 = g_csr[j + 0];
        int2 e1 = g_csr[j + 1];
        int2 e2 = g_csr[j + 2];
        int2 e3 = g_csr[j + 3];
        float4 v0 = ((const float4*)(g_h2 + (size_t)e0.x * D_H2))[lane];
        float4 v1 = ((const float4*)(g_h2 + (size_t)e1.x * D_H2))[lane];
        float4 v2 = ((const float4*)(g_h2 + (size_t)e2.x * D_H2))[lane];
        float4 v3 = ((const float4*)(g_h2 + (size_t)e3.x * D_H2))[lane];
        float w0 = __int_as_float(e0.y);
        float w1 = __int_as_float(e1.y);
        float w2 = __int_as_float(e2.y);
        float w3 = __int_as_float(e3.y);
        acc.x += w0 * v0.x + w1 * v1.x + w2 * v2.x + w3 * v3.x;
        acc.y += w0 * v0.y + w1 * v1.y + w2 * v2.y + w3 * v3.y;
        acc.z += w0 * v0.z + w1 * v1.z + w2 * v2.z + w3 * v3.z;
        acc.w += w0 * v0.w + w1 * v1.w + w2 * v2.w + w3 * v3.w;
    }
    for (; j < end; j++) {
        int2 e = g_csr[j];
        float w = __int_as_float(e.y);
        float4 v = ((const float4*)(g_h2 + (size_t)e.x * D_H2))[lane];
        acc.x += w * v.x;
        acc.y += w * v.y;
        acc.z += w * v.z;
        acc.w += w * v.w;
    }
    float dv = rsqrtf(g_deg[node] + 1.0f);
    float d2 = dv * dv;
    float4 hv = ((const float4*)(g_h2 + (size_t)node * D_H2))[lane];
    float4 bv = ((const float4*)b2)[lane];
    float4 o;
    o.x = fmaxf(acc.x + d2 * hv.x + bv.x, 0.f);
    o.y = fmaxf(acc.y + d2 * hv.y + bv.y, 0.f);
    o.z = fmaxf(acc.z + d2 * hv.z + bv.z, 0.f);
    o.w = fmaxf(acc.w + d2 * hv.w + bv.w, 0.f);
    ((float4*)(g_a2 + (size_t)node * D_H2))[lane] = o;
}

// ---------------- launch ----------------------------------------------------
extern "C" void kernel_launch(void* const* d_in, const int* in_sizes, int n_in,
                              void* d_out, int out_size) {
    const float *x = 0, *ew = 0, *W1 = 0, *b1 = 0, *W2 = 0, *b2 = 0, *Wc = 0, *bc = 0;
    const void* ei = 0;
    for (int i = 0; i < n_in; i++) {
        switch (in_sizes[i]) {
            case N_NODES * D_IN:   x  = (const float*)d_in[i]; break;
            case 2 * E_EDGES:      ei = d_in[i];               break;
            case E_EDGES:          ew = (const float*)d_in[i]; break;
            case D_IN * D_H1:      W1 = (const float*)d_in[i]; break;
            case D_H1:             b1 = (const float*)d_in[i]; break;
            case D_H1 * D_H2:      W2 = (const float*)d_in[i]; break;
            case D_H2:             b2 = (const float*)d_in[i]; break;
            case D_H2 * N_CLS:     Wc = (const float*)d_in[i]; break;
            case N_CLS:            bc = (const float*)d_in[i]; break;
            default: break;
        }
    }
    float* out = (float*)d_out;
    const int T = 256;

    detect_kernel<<<1, 256>>>((const unsigned int*)ei);                 // 1
    zero_bufs<<<(N_NODES + T - 1) / T, T>>>();                          // 2
    convert_deg<<<(E_EDGES + T - 1) / T, T>>>(ei, ew);                  // 3
    gemm_l1<<<dim3((N_NODES + 127) / 128, 1), T>>>(x, W1);              // 4 (profiled)
    scan_kernel<<<1, 1024>>>();                                         // 5
    scatter_kernel<<<(E_EDGES + T - 1) / T, T>>>(ei, ew);               // 6
    agg1<<<(N_NODES * 32 + T - 1) / T, T>>>(b1);                        // 7
    gemm_l2<<<dim3((N_NODES + 127) / 128, 1), T>>>(W2);                 // 8
    agg2<<<(N_NODES * 16 + T - 1) / T, T>>>(b2);                        // 9
    gemm_l3<<<dim3((N_NODES + 63) / 64, 1), T>>>(Wc, bc, out);          // 10
}